// round 3
// baseline (speedup 1.0000x reference)
#include <cuda_runtime.h>

#define CC 64
#define BB 32
#define HH 80
#define WW 80
#define CELL (CC*BB)      // 2048 floats per cell tile
#define NCELLS (HH*WW)    // 6400 cells
#define HPAD 34           // padded ull row stride for splatted h buffers (kills ST bank conflicts)

// Static device scratch (allocation-free per harness rules)
__device__ float g_xT[NCELLS*CELL];          // x transposed to [i][j][c][b]
__device__ float g_hf[4][NCELLS*CELL];       // per-direction h fields, [i][j][c][b]
__device__ int   g_cnt[4][WW];               // rows completed per (dir, internal column)

typedef unsigned long long ull;

// ---------- packed-f32x2 helpers ----------
static __device__ __forceinline__ ull splat2(float x){
  unsigned int r = __float_as_uint(x);
  ull d; asm("mov.b64 %0, {%1,%2};" : "=l"(d) : "r"(r), "r"(r));
  return d;
}
static __device__ __forceinline__ void fma2(ull &d, ull a, ull b){
  asm("fma.rn.f32x2 %0, %1, %2, %0;" : "+l"(d) : "l"(a), "l"(b));
}
static __device__ __forceinline__ void unpack2(ull v, float &lo, float &hi){
  unsigned int a, b;
  asm("mov.b64 {%0,%1}, %2;" : "=r"(a), "=r"(b) : "l"(v));
  lo = __uint_as_float(a); hi = __uint_as_float(b);
}
static __device__ __forceinline__ float lo32(ull v){
  unsigned int a, b;
  asm("mov.b64 {%0,%1}, %2;" : "=r"(a), "=r"(b) : "l"(v));
  return __uint_as_float(a);
}
static __device__ __forceinline__ int ld_acq(const int* p){
  int v; asm volatile("ld.global.acquire.gpu.b32 %0, [%1];" : "=r"(v) : "l"(p)); return v;
}
static __device__ __forceinline__ void st_relx(int* p, int v){
  asm volatile("st.global.relaxed.gpu.b32 [%0], %1;" :: "l"(p), "r"(v));
}
static __device__ __forceinline__ void fence_gpu(){
  asm volatile("fence.acq_rel.gpu;" ::: "memory");
}

// ---------- kernel 1: transpose x [B,C,H,W] -> g_xT [i][j][c][b]; also zero flags ----------
__global__ void __launch_bounds__(256) k_transpose(const float* __restrict__ x){
  int bid = blockIdx.x;              // 800 blocks: (i, j-tile of 8)
  int i  = bid / 10;
  int j0 = (bid % 10) * 8;
  int t  = threadIdx.x;

  if (bid == 0 && t < 4*WW) ((int*)g_cnt)[t] = 0;

  int p0 = t * 8;                    // p = c*32 + b ; 8 consecutive p = fixed c, 8 b's
  int c  = p0 >> 5;
  int b0 = p0 & 31;

  float v[8][8];
  #pragma unroll
  for (int pi = 0; pi < 8; pi++){
    const float* src = x + (((b0+pi)*CC + c)*HH + i)*WW + j0;
    float4 q0 = *(const float4*)src;
    float4 q1 = *(const float4*)(src + 4);
    v[pi][0]=q0.x; v[pi][1]=q0.y; v[pi][2]=q0.z; v[pi][3]=q0.w;
    v[pi][4]=q1.x; v[pi][5]=q1.y; v[pi][6]=q1.z; v[pi][7]=q1.w;
  }
  #pragma unroll
  for (int jj = 0; jj < 8; jj++){
    float* dst = g_xT + (i*WW + j0 + jj)*CELL + p0;
    *(float4*)dst     = make_float4(v[0][jj], v[1][jj], v[2][jj], v[3][jj]);
    *(float4*)(dst+4) = make_float4(v[4][jj], v[5][jj], v[6][jj], v[7][jj]);
  }
}

// ---------- inner matmul over pre-splatted h ----------
// acc(4c x 2b per thread) += G(64x64, transposed [k][c] in smem) @ h(64x32 splatted ull in smem)
// 6 instructions per k: LDS.128 (G c-pair x2), LDS.128 (2 splatted h), 4x FFMA2.
static __device__ __forceinline__ void mm_acc(const float* sG, const ull* hbuf,
    int c0, int b0, ull &a00, ull &a01, ull &a10, ull &a11){
  #pragma unroll 8
  for (int k = 0; k < CC; k++){
    ulonglong2 g = *(const ulonglong2*)(sG + k*CC + c0);       // {G[c0,k],G[c0+1,k]},{G[c0+2,k],G[c0+3,k]}
    ulonglong2 h = *(const ulonglong2*)(hbuf + k*HPAD + b0);   // splat(h[k,b0]), splat(h[k,b0+1])
    fma2(a00, g.x, h.x); fma2(a01, g.y, h.x);
    fma2(a10, g.x, h.y); fma2(a11, g.y, h.y);
  }
}

// ---------- kernel 2: persistent column-pipelined DAG recurrence, 4 dirs x 80 columns ----------
extern __shared__ float smem_dyn[];

__global__ void __launch_bounds__(256, 3) k_dag(
    const float* __restrict__ w0v, const float* __restrict__ w0h,
    const float* __restrict__ w1v, const float* __restrict__ w1h,
    const float* __restrict__ w2v, const float* __restrict__ w2h,
    const float* __restrict__ w3v, const float* __restrict__ w3h)
{
  const int bid  = blockIdx.x;
  const int dir  = bid / WW;        // dependency points to lower bids only -> schedule-safe
  const int jcol = bid % WW;
  const int tid  = threadIdx.x;

  const float* gv; const float* gh;
  int fi, fj, doRelu;
  switch (dir){
    case 0:  gv=w0v; gh=w0h; fi=0; fj=0; doRelu=1; break;  // SE
    case 1:  gv=w1v; gh=w1h; fi=1; fj=0; doRelu=1; break;  // NE
    case 2:  gv=w2v; gh=w2h; fi=1; fj=1; doRelu=1; break;  // NW
    default: gv=w3v; gh=w3h; fi=0; fj=1; doRelu=0; break;  // SW (no ReLU in reference)
  }

  float* sGv = smem_dyn;                      // [k][c] transposed, 4096 f = 16KB
  float* sGh = smem_dyn + 4096;               // [k][c] transposed, 4096 f = 16KB
  ull*   hA  = (ull*)(smem_dyn + 8192);       // own h_prev, splatted, [k][HPAD]
  ull*   hB  = hA + CC*HPAD;                  // left-neighbor h, splatted, [k][HPAD]

  for (int idx = tid; idx < 4096; idx += 256){
    int c = idx >> 6, k = idx & 63;           // idx = c*64 + k (row-major source)
    sGv[k*CC + c] = gv[idx];
    sGh[k*CC + c] = gh[idx];
  }
  for (int idx = tid; idx < CC*HPAD; idx += 256) hA[idx] = 0ull;
  __syncthreads();

  const int cg = tid & 15, bg = tid >> 4;
  const int c0 = cg * 4, b0 = bg * 2;
  const int p0 = tid * 8;                     // compact tile slice: c = p0>>5, b = p0&31
  const int cS = p0 >> 5, bS = p0 & 31;

  float* out_dir = g_hf[dir];
  const int rj  = fj ? (WW-1-jcol) : jcol;    // actual column of this internal column
  const int rjL = fj ? (WW-jcol)   : (jcol-1);// actual column of internal (j-1)
  const int* cleft = &g_cnt[dir][(jcol > 0) ? (jcol-1) : 0];
  int* cme = &g_cnt[dir][jcol];

  for (int i = 0; i < HH; i++){
    const int ri = fi ? (HH-1-i) : i;

    // ---- wait for left neighbor (single-thread acquire spin, no fence storm) ----
    if (jcol > 0 && tid == 0){
      while (ld_acq(cleft) < i + 1) { }
    }
    __syncthreads();                          // B: flag observation broadcast; prev-row hB reads done

    // ---- issue long-latency loads early (hidden under the vertical matmul) ----
    float4 l0, l1;
    if (jcol > 0){
      const float* lcell = out_dir + (ri*WW + rjL)*CELL;
      l0 = *(const float4*)(lcell + p0);
      l1 = *(const float4*)(lcell + p0 + 4);
    }
    const float* xcell = g_xT + (ri*WW + rj)*CELL;
    float2 xv0 = *(const float2*)(xcell + (c0+0)*BB + b0);
    float2 xv1 = *(const float2*)(xcell + (c0+1)*BB + b0);
    float2 xv2 = *(const float2*)(xcell + (c0+2)*BB + b0);
    float2 xv3 = *(const float2*)(xcell + (c0+3)*BB + b0);

    ull a00 = 0, a01 = 0, a10 = 0, a11 = 0;

    // ---- vertical matmul: Gv @ h_prev (in-CTA, SMEM-resident) ----
    mm_acc(sGv, hA, c0, b0, a00, a01, a10, a11);

    // ---- stage left cell into hB, splatted ----
    if (jcol > 0){
      ull* dst = hB + cS*HPAD + bS;
      ulonglong2 v;
      v.x = splat2(l0.x); v.y = splat2(l0.y); *(ulonglong2*)(dst + 0) = v;
      v.x = splat2(l0.z); v.y = splat2(l0.w); *(ulonglong2*)(dst + 2) = v;
      v.x = splat2(l1.x); v.y = splat2(l1.y); *(ulonglong2*)(dst + 4) = v;
      v.x = splat2(l1.z); v.y = splat2(l1.w); *(ulonglong2*)(dst + 6) = v;
    }
    __syncthreads();                          // F: hB ready

    if (jcol > 0){
      mm_acc(sGh, hB, c0, b0, a00, a01, a10, a11);
    }

    // ---- epilogue: unpack, +x, (ReLU) ----
    float oc[4][2];
    unpack2(a00, oc[0][0], oc[1][0]);
    unpack2(a01, oc[2][0], oc[3][0]);
    unpack2(a10, oc[0][1], oc[1][1]);
    unpack2(a11, oc[2][1], oc[3][1]);
    oc[0][0] += xv0.x; oc[0][1] += xv0.y;
    oc[1][0] += xv1.x; oc[1][1] += xv1.y;
    oc[2][0] += xv2.x; oc[2][1] += xv2.y;
    oc[3][0] += xv3.x; oc[3][1] += xv3.y;
    if (doRelu){
      #pragma unroll
      for (int r = 0; r < 4; r++){
        oc[r][0] = fmaxf(oc[r][0], 0.f);
        oc[r][1] = fmaxf(oc[r][1], 0.f);
      }
    }

    // ---- h -> hA splatted (becomes h_prev for next row) ----
    #pragma unroll
    for (int r = 0; r < 4; r++){
      ulonglong2 v; v.x = splat2(oc[r][0]); v.y = splat2(oc[r][1]);
      *(ulonglong2*)(hA + (c0+r)*HPAD + b0) = v;
    }
    __syncthreads();                          // I: hA tile complete

    // ---- coalesced compact publish for right neighbor + final sum ----
    {
      const ull* src = hA + cS*HPAD + bS;
      ulonglong2 u0 = *(const ulonglong2*)(src + 0);
      ulonglong2 u1 = *(const ulonglong2*)(src + 2);
      ulonglong2 u2 = *(const ulonglong2*)(src + 4);
      ulonglong2 u3 = *(const ulonglong2*)(src + 6);
      float* ocell = out_dir + (ri*WW + rj)*CELL + p0;
      *(float4*)(ocell)     = make_float4(lo32(u0.x), lo32(u0.y), lo32(u1.x), lo32(u1.y));
      *(float4*)(ocell + 4) = make_float4(lo32(u2.x), lo32(u2.y), lo32(u3.x), lo32(u3.y));
    }
    __syncthreads();                          // K: all STGs ordered before the fence below
    if (tid == 0){
      fence_gpu();                            // cumulative gpu-scope fence (covers all threads' STGs)
      st_relx(cme, i + 1);                    // publish row counter
    }
  }
}

// ---------- kernel 3: out[b][c][i][j] = sum over 4 dirs of g_hf[d][i][j][c][b] ----------
__global__ void __launch_bounds__(256) k_sum(float* __restrict__ out){
  int bid = blockIdx.x;              // 800 blocks: (i, j-tile of 8)
  int i  = bid / 10;
  int j0 = (bid % 10) * 8;
  int t  = threadIdx.x;
  int p0 = t * 8;                    // fixed c, 8 consecutive b
  int c  = p0 >> 5;
  int b0 = p0 & 31;

  float v[8][8];
  #pragma unroll
  for (int jj = 0; jj < 8; jj++){
    int cell = (i*WW + j0 + jj)*CELL;
    float4 s0 = make_float4(0.f,0.f,0.f,0.f);
    float4 s1 = make_float4(0.f,0.f,0.f,0.f);
    #pragma unroll
    for (int d = 0; d < 4; d++){
      const float* src = g_hf[d] + cell + p0;
      float4 q0 = *(const float4*)src;
      float4 q1 = *(const float4*)(src + 4);
      s0.x += q0.x; s0.y += q0.y; s0.z += q0.z; s0.w += q0.w;
      s1.x += q1.x; s1.y += q1.y; s1.z += q1.z; s1.w += q1.w;
    }
    v[0][jj]=s0.x; v[1][jj]=s0.y; v[2][jj]=s0.z; v[3][jj]=s0.w;
    v[4][jj]=s1.x; v[5][jj]=s1.y; v[6][jj]=s1.z; v[7][jj]=s1.w;
  }
  #pragma unroll
  for (int pi = 0; pi < 8; pi++){
    float* dst = out + ((b0+pi)*CC + c)*NCELLS + i*WW + j0;
    *(float4*)dst     = make_float4(v[pi][0], v[pi][1], v[pi][2], v[pi][3]);
    *(float4*)(dst+4) = make_float4(v[pi][4], v[pi][5], v[pi][6], v[pi][7]);
  }
}

extern "C" void kernel_launch(void* const* d_in, const int* in_sizes, int n_in,
                              void* d_out, int out_size){
  const float* x   = (const float*)d_in[0];
  const float* g1  = (const float*)d_in[1];
  const float* g2  = (const float*)d_in[2];
  const float* g4  = (const float*)d_in[3];
  const float* g5  = (const float*)d_in[4];
  const float* g7  = (const float*)d_in[5];
  const float* g8  = (const float*)d_in[6];
  const float* g10 = (const float*)d_in[7];
  const float* g11 = (const float*)d_in[8];

  const int smem_bytes = 8192*4 + 2*CC*HPAD*8;   // 32KB weights + 2 splatted h buffers = 67584B
  (void)cudaFuncSetAttribute(k_dag, cudaFuncAttributeMaxDynamicSharedMemorySize, smem_bytes);

  k_transpose<<<800, 256>>>(x);
  k_dag<<<320, 256, smem_bytes>>>(g1, g2, g4, g5, g7, g8, g10, g11);
  k_sum<<<800, 256>>>((float*)d_out);
}

// round 4
// speedup vs baseline: 1.3396x; 1.3396x over previous
#include <cuda_runtime.h>

#define CC 64
#define BB 32
#define HH 80
#define WW 80
#define CELL (CC*BB)      // 2048 floats per cell tile
#define NCELLS (HH*WW)    // 6400 cells
#define GS 68             // G smem row stride (floats): conflict-free reads, 16B-aligned
#define HS 36             // h smem row stride (floats): 16B-aligned, low-conflict

// Static device scratch (allocation-free per harness rules)
__device__ float g_xT[NCELLS*CELL];          // x transposed to [i][j][c][b]
__device__ float g_hf[4][NCELLS*CELL];       // per-direction h fields, [i][j][c][b]
__device__ int   g_cnt[4][WW][4];            // per-(dir,col,warp) rows-completed flags

typedef unsigned long long ull;

// ---------- packed-f32x2 helpers ----------
static __device__ __forceinline__ ull splat2(float x){
  unsigned int r = __float_as_uint(x);
  ull d; asm("mov.b64 %0, {%1,%2};" : "=l"(d) : "r"(r), "r"(r));
  return d;
}
static __device__ __forceinline__ void fma2(ull &d, ull a, ull b){
  asm("fma.rn.f32x2 %0, %1, %2, %0;" : "+l"(d) : "l"(a), "l"(b));
}
static __device__ __forceinline__ void unpack2(ull v, float &lo, float &hi){
  unsigned int a, b;
  asm("mov.b64 {%0,%1}, %2;" : "=r"(a), "=r"(b) : "l"(v));
  lo = __uint_as_float(a); hi = __uint_as_float(b);
}
static __device__ __forceinline__ int ld_acq(const int* p){
  int v; asm volatile("ld.global.acquire.gpu.b32 %0, [%1];" : "=r"(v) : "l"(p)); return v;
}
static __device__ __forceinline__ void st_rel(int* p, int v){
  asm volatile("st.global.release.gpu.b32 [%0], %1;" :: "l"(p), "r"(v));
}

// ---------- kernel 1: transpose x [B,C,H,W] -> g_xT [i][j][c][b]; zero flags ----------
__global__ void __launch_bounds__(256) k_transpose(const float* __restrict__ x){
  int bid = blockIdx.x;              // 800 blocks: (i, j-tile of 8)
  int i  = bid / 10;
  int j0 = (bid % 10) * 8;
  int t  = threadIdx.x;

  if (bid == 0){
    for (int z = t; z < 4*WW*4; z += 256) ((int*)g_cnt)[z] = 0;
  }

  int p0 = t * 8;                    // p = c*32 + b ; 8 consecutive p = fixed c, 8 b's
  int c  = p0 >> 5;
  int b0 = p0 & 31;

  float v[8][8];
  #pragma unroll
  for (int pi = 0; pi < 8; pi++){
    const float* src = x + (((b0+pi)*CC + c)*HH + i)*WW + j0;
    float4 q0 = *(const float4*)src;
    float4 q1 = *(const float4*)(src + 4);
    v[pi][0]=q0.x; v[pi][1]=q0.y; v[pi][2]=q0.z; v[pi][3]=q0.w;
    v[pi][4]=q1.x; v[pi][5]=q1.y; v[pi][6]=q1.z; v[pi][7]=q1.w;
  }
  #pragma unroll
  for (int jj = 0; jj < 8; jj++){
    float* dst = g_xT + (i*WW + j0 + jj)*CELL + p0;
    *(float4*)dst     = make_float4(v[0][jj], v[1][jj], v[2][jj], v[3][jj]);
    *(float4*)(dst+4) = make_float4(v[4][jj], v[5][jj], v[6][jj], v[7][jj]);
  }
}

// ---------- inner matmul ----------
// Thread tile 4c x 4b. G transposed [k][c] in smem (natural floats, splat in-register);
// h natural [k][b] in smem, read as ulonglong2 = two packed f32x2 pairs directly.
// 14 instr per 32 FMA: 2x LDS.128 + 4x MOV(splat) + 8x FFMA2.
static __device__ __forceinline__ void mm_acc(const float* __restrict__ sG,
    const float* __restrict__ hb, int c0, int b0, ull a[4][2]){
  #pragma unroll 8
  for (int k = 0; k < CC; k++){
    float4 gq = *(const float4*)(sG + k*GS + c0);
    ulonglong2 hq = *(const ulonglong2*)(hb + k*HS + b0);
    ull g0 = splat2(gq.x), g1 = splat2(gq.y), g2 = splat2(gq.z), g3 = splat2(gq.w);
    fma2(a[0][0], g0, hq.x); fma2(a[0][1], g0, hq.y);
    fma2(a[1][0], g1, hq.x); fma2(a[1][1], g1, hq.y);
    fma2(a[2][0], g2, hq.x); fma2(a[2][1], g2, hq.y);
    fma2(a[3][0], g3, hq.x); fma2(a[3][1], g3, hq.y);
  }
}

// ---------- kernel 2: persistent column-pipelined DAG recurrence, 4 dirs x 80 columns ----------
extern __shared__ float smem_dyn[];

__global__ void __launch_bounds__(128, 3) k_dag(
    const float* __restrict__ w0v, const float* __restrict__ w0h,
    const float* __restrict__ w1v, const float* __restrict__ w1h,
    const float* __restrict__ w2v, const float* __restrict__ w2h,
    const float* __restrict__ w3v, const float* __restrict__ w3h)
{
  const int bid  = blockIdx.x;
  const int dir  = bid / WW;        // dependency points to lower bids only -> schedule-safe
  const int jcol = bid % WW;
  const int tid  = threadIdx.x;

  const float* gv; const float* gh;
  int fi, fj, doRelu;
  switch (dir){
    case 0:  gv=w0v; gh=w0h; fi=0; fj=0; doRelu=1; break;  // SE
    case 1:  gv=w1v; gh=w1h; fi=1; fj=0; doRelu=1; break;  // NE
    case 2:  gv=w2v; gh=w2h; fi=1; fj=1; doRelu=1; break;  // NW
    default: gv=w3v; gh=w3h; fi=0; fj=1; doRelu=0; break;  // SW (no ReLU in reference)
  }

  float* sGv   = smem_dyn;                 // [k][c] transposed, 64*GS floats
  float* sGh   = smem_dyn + CC*GS;
  float* hbase = smem_dyn + 2*CC*GS;       // 4 h buffers of CC*HS floats each:
                                           // hA0, hA1, hB0, hB1

  for (int idx = tid; idx < 4096; idx += 128){
    int c = idx >> 6, k = idx & 63;        // idx = c*64 + k (row-major source)
    sGv[k*GS + c] = gv[idx];
    sGh[k*GS + c] = gh[idx];
  }
  for (int idx = tid; idx < CC*HS; idx += 128) hbase[idx] = 0.f;   // zero hA0
  __syncthreads();

  // warp tiling: warp covers 32c x 16b; thread covers 4c x 4b
  const int lane = tid & 31, w = tid >> 5;
  const int cpart = w >> 1, bpart = w & 1;
  const int cg = lane >> 2, bp = lane & 3;
  const int c0 = cpart*32 + cg*4;
  const int b0 = bpart*16 + bp*4;
  // linear staging slice: 16 consecutive floats per thread
  const int kS = tid >> 1;
  const int bS = (tid & 1) * 16;

  float* out_dir = g_hf[dir];
  const int rj  = fj ? (WW-1-jcol) : jcol;
  const int rjL = fj ? (WW-jcol)   : (jcol-1);
  const int* cleft = g_cnt[dir][(jcol > 0) ? (jcol-1) : 0];
  int* cme = g_cnt[dir][jcol];

  for (int i = 0; i < HH; i++){
    const int ri = fi ? (HH-1-i) : i;

    // ---- wait for left neighbor's 4 warp-flags, then stage its cell into hB (pre-bar) ----
    if (jcol > 0){
      const int need = i + 1;
      while (ld_acq(cleft+0) < need || ld_acq(cleft+1) < need ||
             ld_acq(cleft+2) < need || ld_acq(cleft+3) < need) { }
      const float* lcell = out_dir + (ri*WW + rjL)*CELL + tid*16;
      float4 l0 = *(const float4*)(lcell);
      float4 l1 = *(const float4*)(lcell + 4);
      float4 l2 = *(const float4*)(lcell + 8);
      float4 l3 = *(const float4*)(lcell + 12);
      float* hB = hbase + (2 + (i&1))*CC*HS + kS*HS + bS;
      *(float4*)(hB + 0)  = l0;
      *(float4*)(hB + 4)  = l1;
      *(float4*)(hB + 8)  = l2;
      *(float4*)(hB + 12) = l3;
    }
    __syncthreads();                       // ONE bar per row: hB(i) + hA(i) visible

    const float* hA  = hbase + (i&1)*CC*HS;
    const float* hBr = hbase + (2 + (i&1))*CC*HS;
    const float* xcell = g_xT + (ri*WW + rj)*CELL;

    // acc init = x tile (ulonglong2 reinterpret = already-packed f32x2 pairs)
    ull a[4][2];
    #pragma unroll
    for (int r = 0; r < 4; r++){
      ulonglong2 xu = *(const ulonglong2*)(xcell + (c0+r)*BB + b0);
      a[r][0] = xu.x; a[r][1] = xu.y;
    }

    mm_acc(sGv, hA, c0, b0, a);            // vertical: Gv @ h_prev
    if (jcol > 0)
      mm_acc(sGh, hBr, c0, b0, a);         // horizontal: Gh @ h_left

    // epilogue: unpack, (ReLU), write next hA + publish to gmem straight from regs
    float* hAn = hbase + ((i+1)&1)*CC*HS;
    float* ocell = out_dir + (ri*WW + rj)*CELL;
    #pragma unroll
    for (int r = 0; r < 4; r++){
      float o0, o1, o2, o3;
      unpack2(a[r][0], o0, o1);
      unpack2(a[r][1], o2, o3);
      if (doRelu){
        o0 = fmaxf(o0, 0.f); o1 = fmaxf(o1, 0.f);
        o2 = fmaxf(o2, 0.f); o3 = fmaxf(o3, 0.f);
      }
      float4 o = make_float4(o0, o1, o2, o3);
      *(float4*)(hAn + (c0+r)*HS + b0) = o;
      *(float4*)(ocell + (c0+r)*BB + b0) = o;
    }

    // per-warp release flag: syncwarp orders the warp's STGs under lane0's release
    __syncwarp();
    if (lane == 0) st_rel(&cme[w], i + 1);
  }
}

// ---------- kernel 3: out[b][c][i][j] = sum over 4 dirs of g_hf[d][i][j][c][b] ----------
__global__ void __launch_bounds__(256) k_sum(float* __restrict__ out){
  int bid = blockIdx.x;              // 800 blocks: (i, j-tile of 8)
  int i  = bid / 10;
  int j0 = (bid % 10) * 8;
  int t  = threadIdx.x;
  int p0 = t * 8;                    // fixed c, 8 consecutive b
  int c  = p0 >> 5;
  int b0 = p0 & 31;

  float v[8][8];
  #pragma unroll
  for (int jj = 0; jj < 8; jj++){
    int cell = (i*WW + j0 + jj)*CELL;
    float4 s0 = make_float4(0.f,0.f,0.f,0.f);
    float4 s1 = make_float4(0.f,0.f,0.f,0.f);
    #pragma unroll
    for (int d = 0; d < 4; d++){
      const float* src = g_hf[d] + cell + p0;
      float4 q0 = *(const float4*)src;
      float4 q1 = *(const float4*)(src + 4);
      s0.x += q0.x; s0.y += q0.y; s0.z += q0.z; s0.w += q0.w;
      s1.x += q1.x; s1.y += q1.y; s1.z += q1.z; s1.w += q1.w;
    }
    v[0][jj]=s0.x; v[1][jj]=s0.y; v[2][jj]=s0.z; v[3][jj]=s0.w;
    v[4][jj]=s1.x; v[5][jj]=s1.y; v[6][jj]=s1.z; v[7][jj]=s1.w;
  }
  #pragma unroll
  for (int pi = 0; pi < 8; pi++){
    float* dst = out + ((b0+pi)*CC + c)*NCELLS + i*WW + j0;
    *(float4*)dst     = make_float4(v[pi][0], v[pi][1], v[pi][2], v[pi][3]);
    *(float4*)(dst+4) = make_float4(v[pi][4], v[pi][5], v[pi][6], v[pi][7]);
  }
}

extern "C" void kernel_launch(void* const* d_in, const int* in_sizes, int n_in,
                              void* d_out, int out_size){
  const float* x   = (const float*)d_in[0];
  const float* g1  = (const float*)d_in[1];
  const float* g2  = (const float*)d_in[2];
  const float* g4  = (const float*)d_in[3];
  const float* g5  = (const float*)d_in[4];
  const float* g7  = (const float*)d_in[5];
  const float* g8  = (const float*)d_in[6];
  const float* g10 = (const float*)d_in[7];
  const float* g11 = (const float*)d_in[8];

  const int smem_bytes = (2*CC*GS + 4*CC*HS) * 4;   // 34,816 + 36,864 = 71,680 B
  (void)cudaFuncSetAttribute(k_dag, cudaFuncAttributeMaxDynamicSharedMemorySize, smem_bytes);

  k_transpose<<<800, 256>>>(x);
  k_dag<<<320, 128, smem_bytes>>>(g1, g2, g4, g5, g7, g8, g10, g11);
  k_sum<<<800, 256>>>((float*)d_out);
}

// round 7
// speedup vs baseline: 1.6505x; 1.2321x over previous
#include <cuda_runtime.h>

#define CC 64
#define BB 32
#define HH 80
#define WW 80
#define CELL (CC*BB)      // 2048 floats per cell tile
#define NCELLS (HH*WW)    // 6400 cells
#define GSU 66            // splatted-G smem row stride in ull (16B aligned, conflict-benign)
#define HS 36             // h smem row stride in floats (16B aligned)

// Static device scratch (allocation-free per harness rules)
__device__ float g_xT[NCELLS*CELL];          // x transposed to [i][j][c][b]
__device__ float g_hf[4][NCELLS*CELL];       // per-direction h fields, [i][j][c][b]
__device__ int   g_cnt[4][WW][4];            // per-(dir,col,warp) rows-completed flags

typedef unsigned long long ull;

// ---------- packed-f32x2 helpers ----------
static __device__ __forceinline__ ull splat2(float x){
  unsigned int r = __float_as_uint(x);
  ull d; asm("mov.b64 %0, {%1,%2};" : "=l"(d) : "r"(r), "r"(r));
  return d;
}
static __device__ __forceinline__ void fma2(ull &d, ull a, ull b){
  asm("fma.rn.f32x2 %0, %1, %2, %0;" : "+l"(d) : "l"(a), "l"(b));
}
static __device__ __forceinline__ void unpack2(ull v, float &lo, float &hi){
  unsigned int a, b;
  asm("mov.b64 {%0,%1}, %2;" : "=r"(a), "=r"(b) : "l"(v));
  lo = __uint_as_float(a); hi = __uint_as_float(b);
}
static __device__ __forceinline__ int ld_acq(const int* p){
  int v; asm volatile("ld.global.acquire.gpu.b32 %0, [%1];" : "=r"(v) : "l"(p)); return v;
}
static __device__ __forceinline__ void st_rel(int* p, int v){
  asm volatile("st.global.release.gpu.b32 [%0], %1;" :: "l"(p), "r"(v));
}

// ---------- kernel 1: transpose x [B,C,H,W] -> g_xT [i][j][c][b]; zero flags ----------
__global__ void __launch_bounds__(256) k_transpose(const float* __restrict__ x){
  int bid = blockIdx.x;              // 800 blocks: (i, j-tile of 8)
  int i  = bid / 10;
  int j0 = (bid % 10) * 8;
  int t  = threadIdx.x;

  if (bid == 0){
    for (int z = t; z < 4*WW*4; z += 256) ((int*)g_cnt)[z] = 0;
  }

  int p0 = t * 8;                    // p = c*32 + b ; 8 consecutive p = fixed c, 8 b's
  int c  = p0 >> 5;
  int b0 = p0 & 31;

  float v[8][8];
  #pragma unroll
  for (int pi = 0; pi < 8; pi++){
    const float* src = x + (((b0+pi)*CC + c)*HH + i)*WW + j0;
    float4 q0 = *(const float4*)src;
    float4 q1 = *(const float4*)(src + 4);
    v[pi][0]=q0.x; v[pi][1]=q0.y; v[pi][2]=q0.z; v[pi][3]=q0.w;
    v[pi][4]=q1.x; v[pi][5]=q1.y; v[pi][6]=q1.z; v[pi][7]=q1.w;
  }
  #pragma unroll
  for (int jj = 0; jj < 8; jj++){
    float* dst = g_xT + (i*WW + j0 + jj)*CELL + p0;
    *(float4*)dst     = make_float4(v[0][jj], v[1][jj], v[2][jj], v[3][jj]);
    *(float4*)(dst+4) = make_float4(v[4][jj], v[5][jj], v[6][jj], v[7][jj]);
  }
}

// ---------- inner matmul with pre-splatted G ----------
// Thread tile 4c x 4b. G pre-splatted [k][c] as ull in smem; h natural [k][b] floats,
// read as ulonglong2 = two packed f32x2 pairs. 11 instr per 32 FMA:
// 3x LDS.128 + 8x FFMA2.
// Acc layout (R4-proven): a[r][0] = row c0+r x (b0,b0+1) ; a[r][1] = row c0+r x (b0+2,b0+3).
static __device__ __forceinline__ void mm_acc(const ull* __restrict__ sG,
    const float* __restrict__ hb, int c0, int b0, ull a[4][2]){
  #pragma unroll 8
  for (int k = 0; k < CC; k++){
    ulonglong2 g01 = *(const ulonglong2*)(sG + k*GSU + c0);      // splat G[c0,k], G[c0+1,k]
    ulonglong2 g23 = *(const ulonglong2*)(sG + k*GSU + c0 + 2);  // splat G[c0+2,k], G[c0+3,k]
    ulonglong2 hq  = *(const ulonglong2*)(hb + k*HS + b0);       // pairs (b0,b0+1),(b0+2,b0+3)
    fma2(a[0][0], g01.x, hq.x); fma2(a[0][1], g01.x, hq.y);
    fma2(a[1][0], g01.y, hq.x); fma2(a[1][1], g01.y, hq.y);
    fma2(a[2][0], g23.x, hq.x); fma2(a[2][1], g23.x, hq.y);
    fma2(a[3][0], g23.y, hq.x); fma2(a[3][1], g23.y, hq.y);
  }
}

// ---------- kernel 2: persistent column-pipelined DAG recurrence, 4 dirs x 80 columns ----------
extern __shared__ float smem_dyn[];

__global__ void __launch_bounds__(128, 2) k_dag(
    const float* __restrict__ w0v, const float* __restrict__ w0h,
    const float* __restrict__ w1v, const float* __restrict__ w1h,
    const float* __restrict__ w2v, const float* __restrict__ w2h,
    const float* __restrict__ w3v, const float* __restrict__ w3h)
{
  const int bid  = blockIdx.x;
  const int dir  = bid / WW;        // dependency points to lower bids only -> schedule-safe
  const int jcol = bid % WW;
  const int tid  = threadIdx.x;

  const float* gv; const float* gh;
  int fi, fj, doRelu;
  switch (dir){
    case 0:  gv=w0v; gh=w0h; fi=0; fj=0; doRelu=1; break;  // SE
    case 1:  gv=w1v; gh=w1h; fi=1; fj=0; doRelu=1; break;  // NE
    case 2:  gv=w2v; gh=w2h; fi=1; fj=1; doRelu=1; break;  // NW
    default: gv=w3v; gh=w3h; fi=0; fj=1; doRelu=0; break;  // SW (no ReLU in reference)
  }

  ull*   sGv   = (ull*)smem_dyn;            // [k][c] splatted, CC*GSU ull
  ull*   sGh   = sGv + CC*GSU;
  float* hbase = (float*)(sGh + CC*GSU);    // 4 h buffers of CC*HS floats: hA0,hA1,hB0,hB1

  for (int idx = tid; idx < 4096; idx += 128){
    int c = idx >> 6, k = idx & 63;         // idx = c*64 + k (row-major source)
    sGv[k*GSU + c] = splat2(gv[idx]);
    sGh[k*GSU + c] = splat2(gh[idx]);
  }
  for (int idx = tid; idx < CC*HS; idx += 128) hbase[idx] = 0.f;   // zero hA0
  __syncthreads();

  // warp tiling: warp covers 32c x 16b; thread covers 4c x 4b
  const int lane = tid & 31, w = tid >> 5;
  const int cpart = w >> 1, bpart = w & 1;
  const int cg = lane >> 2, bp = lane & 3;
  const int c0 = cpart*32 + cg*4;
  const int b0 = bpart*16 + bp*4;
  // linear staging slice: 16 consecutive floats per thread
  const int kS = tid >> 1;
  const int bS = (tid & 1) * 16;

  float* out_dir = g_hf[dir];
  const int rj  = fj ? (WW-1-jcol) : jcol;
  const int rjL = fj ? (WW-jcol)   : (jcol-1);
  const int* cleft = g_cnt[dir][(jcol > 0) ? (jcol-1) : 0];
  int* cme = g_cnt[dir][jcol];

  for (int i = 0; i < HH; i++){
    const int ri = fi ? (HH-1-i) : i;
    const float* hA  = hbase + (i&1)*CC*HS;
    float*       hB  = hbase + (2 + (i&1))*CC*HS;
    const float* xcell = g_xT + (ri*WW + rj)*CELL;

    // ---- acc init = x tile, matching mm_acc layout:
    // a[r][0] = x[c0+r][b0,b0+1], a[r][1] = x[c0+r][b0+2,b0+3]
    ull a[4][2];
    #pragma unroll
    for (int r = 0; r < 4; r++){
      ulonglong2 xu = *(const ulonglong2*)(xcell + (c0+r)*BB + b0);
      a[r][0] = xu.x; a[r][1] = xu.y;
    }

    // ---- vertical matmul FIRST (off the inter-column chain) ----
    mm_acc(sGv, hA, c0, b0, a);

    // ---- wait for left neighbor, stage its cell ----
    if (jcol > 0){
      const int need = i + 1;
      int f0, f1, f2, f3;
      do {                                   // 4 independent acquire loads -> one L2 RTT/iter
        f0 = ld_acq(cleft+0); f1 = ld_acq(cleft+1);
        f2 = ld_acq(cleft+2); f3 = ld_acq(cleft+3);
      } while (min(min(f0,f1), min(f2,f3)) < need);

      const float* lcell = out_dir + (ri*WW + rjL)*CELL + tid*16;
      float4 l0 = *(const float4*)(lcell);
      float4 l1 = *(const float4*)(lcell + 4);
      float4 l2 = *(const float4*)(lcell + 8);
      float4 l3 = *(const float4*)(lcell + 12);
      float* dst = hB + kS*HS + bS;
      *(float4*)(dst + 0)  = l0;
      *(float4*)(dst + 4)  = l1;
      *(float4*)(dst + 8)  = l2;
      *(float4*)(dst + 12) = l3;
      __syncthreads();                       // bar A: hB fully staged (uniform branch: jcol is CTA-wide)
      mm_acc(sGh, hB, c0, b0, a);
    }

    // ---- epilogue (R4-proven mapping): unpack, ReLU ----
    float o[4][4];                           // o[r][bb] = h[c0+r][b0+bb]
    #pragma unroll
    for (int r = 0; r < 4; r++){
      unpack2(a[r][0], o[r][0], o[r][1]);
      unpack2(a[r][1], o[r][2], o[r][3]);
    }
    if (doRelu){
      #pragma unroll
      for (int r = 0; r < 4; r++)
        #pragma unroll
        for (int bb = 0; bb < 4; bb++)
          o[r][bb] = fmaxf(o[r][bb], 0.f);
    }

    // ---- publish to gmem FIRST, release flag, then local smem writeback ----
    float* ocell = out_dir + (ri*WW + rj)*CELL;
    #pragma unroll
    for (int r = 0; r < 4; r++)
      *(float4*)(ocell + (c0+r)*BB + b0) = make_float4(o[r][0], o[r][1], o[r][2], o[r][3]);
    __syncwarp();                            // orders all lanes' STGs before lane0's release
    if (lane == 0) st_rel(&cme[w], i + 1);   // per-warp release

    float* hAn = hbase + ((i+1)&1)*CC*HS;
    #pragma unroll
    for (int r = 0; r < 4; r++)
      *(float4*)(hAn + (c0+r)*HS + b0) = make_float4(o[r][0], o[r][1], o[r][2], o[r][3]);
    __syncthreads();                         // bar B: hA-next complete before next row's mmGv
  }
}

// ---------- kernel 3: out[b][c][i][j] = sum over 4 dirs of g_hf[d][i][j][c][b] ----------
__global__ void __launch_bounds__(256) k_sum(float* __restrict__ out){
  int bid = blockIdx.x;              // 800 blocks: (i, j-tile of 8)
  int i  = bid / 10;
  int j0 = (bid % 10) * 8;
  int t  = threadIdx.x;
  int p0 = t * 8;                    // fixed c, 8 consecutive b
  int c  = p0 >> 5;
  int b0 = p0 & 31;

  float v[8][8];
  #pragma unroll
  for (int jj = 0; jj < 8; jj++){
    int cell = (i*WW + j0 + jj)*CELL;
    float4 s0 = make_float4(0.f,0.f,0.f,0.f);
    float4 s1 = make_float4(0.f,0.f,0.f,0.f);
    #pragma unroll
    for (int d = 0; d < 4; d++){
      const float* src = g_hf[d] + cell + p0;
      float4 q0 = *(const float4*)src;
      float4 q1 = *(const float4*)(src + 4);
      s0.x += q0.x; s0.y += q0.y; s0.z += q0.z; s0.w += q0.w;
      s1.x += q1.x; s1.y += q1.y; s1.z += q1.z; s1.w += q1.w;
    }
    v[0][jj]=s0.x; v[1][jj]=s0.y; v[2][jj]=s0.z; v[3][jj]=s0.w;
    v[4][jj]=s1.x; v[5][jj]=s1.y; v[6][jj]=s1.z; v[7][jj]=s1.w;
  }
  #pragma unroll
  for (int pi = 0; pi < 8; pi++){
    float* dst = out + ((b0+pi)*CC + c)*NCELLS + i*WW + j0;
    *(float4*)dst     = make_float4(v[pi][0], v[pi][1], v[pi][2], v[pi][3]);
    *(float4*)(dst+4) = make_float4(v[pi][4], v[pi][5], v[pi][6], v[pi][7]);
  }
}

extern "C" void kernel_launch(void* const* d_in, const int* in_sizes, int n_in,
                              void* d_out, int out_size){
  const float* x   = (const float*)d_in[0];
  const float* g1  = (const float*)d_in[1];
  const float* g2  = (const float*)d_in[2];
  const float* g4  = (const float*)d_in[3];
  const float* g5  = (const float*)d_in[4];
  const float* g7  = (const float*)d_in[5];
  const float* g8  = (const float*)d_in[6];
  const float* g10 = (const float*)d_in[7];
  const float* g11 = (const float*)d_in[8];

  const int smem_bytes = 2*CC*GSU*8 + 4*CC*HS*4;   // 67,584 + 36,864 = 104,448 B
  (void)cudaFuncSetAttribute(k_dag, cudaFuncAttributeMaxDynamicSharedMemorySize, smem_bytes);

  k_transpose<<<800, 256>>>(x);
  k_dag<<<320, 128, smem_bytes>>>(g1, g2, g4, g5, g7, g8, g10, g11);
  k_sum<<<800, 256>>>((float*)d_out);
}

// round 8
// speedup vs baseline: 1.8003x; 1.0908x over previous
#include <cuda_runtime.h>

#define CC 64
#define BB 32
#define HH 80
#define WW 80
#define CELL (CC*BB)      // 2048 floats per cell tile
#define NCELLS (HH*WW)    // 6400 cells
#define GSU 66            // splatted-G smem row stride in ull (16B aligned)
#define HS2 20            // half h-buffer row stride in floats (80B, 16B-aligned)

// Static device scratch (allocation-free per harness rules)
__device__ float g_xT[NCELLS*CELL];          // x transposed to [i][j][c][b]
__device__ float g_hf[4][NCELLS*CELL];       // per-direction h fields, [i][j][c][b]
__device__ int   g_cnt[4][WW][4];            // per-(dir,col,warp) rows-completed flags

typedef unsigned long long ull;

// ---------- packed-f32x2 helpers ----------
static __device__ __forceinline__ ull splat2(float x){
  unsigned int r = __float_as_uint(x);
  ull d; asm("mov.b64 %0, {%1,%2};" : "=l"(d) : "r"(r), "r"(r));
  return d;
}
static __device__ __forceinline__ void fma2(ull &d, ull a, ull b){
  asm("fma.rn.f32x2 %0, %1, %2, %0;" : "+l"(d) : "l"(a), "l"(b));
}
static __device__ __forceinline__ void unpack2(ull v, float &lo, float &hi){
  unsigned int a, b;
  asm("mov.b64 {%0,%1}, %2;" : "=r"(a), "=r"(b) : "l"(v));
  lo = __uint_as_float(a); hi = __uint_as_float(b);
}
static __device__ __forceinline__ int ld_acq(const int* p){
  int v; asm volatile("ld.global.acquire.gpu.b32 %0, [%1];" : "=r"(v) : "l"(p)); return v;
}
static __device__ __forceinline__ void st_rel(int* p, int v){
  asm volatile("st.global.release.gpu.b32 [%0], %1;" :: "l"(p), "r"(v));
}
static __device__ __forceinline__ void named_bar(int id){
  asm volatile("bar.sync %0, 64;" :: "r"(id) : "memory");
}

// ---------- kernel 1: transpose x [B,C,H,W] -> g_xT [i][j][c][b]; zero flags ----------
__global__ void __launch_bounds__(256) k_transpose(const float* __restrict__ x){
  int bid = blockIdx.x;              // 800 blocks: (i, j-tile of 8)
  int i  = bid / 10;
  int j0 = (bid % 10) * 8;
  int t  = threadIdx.x;

  if (bid == 0){
    for (int z = t; z < 4*WW*4; z += 256) ((int*)g_cnt)[z] = 0;
  }

  int p0 = t * 8;                    // p = c*32 + b ; 8 consecutive p = fixed c, 8 b's
  int c  = p0 >> 5;
  int b0 = p0 & 31;

  float v[8][8];
  #pragma unroll
  for (int pi = 0; pi < 8; pi++){
    const float* src = x + (((b0+pi)*CC + c)*HH + i)*WW + j0;
    float4 q0 = *(const float4*)src;
    float4 q1 = *(const float4*)(src + 4);
    v[pi][0]=q0.x; v[pi][1]=q0.y; v[pi][2]=q0.z; v[pi][3]=q0.w;
    v[pi][4]=q1.x; v[pi][5]=q1.y; v[pi][6]=q1.z; v[pi][7]=q1.w;
  }
  #pragma unroll
  for (int jj = 0; jj < 8; jj++){
    float* dst = g_xT + (i*WW + j0 + jj)*CELL + p0;
    *(float4*)dst     = make_float4(v[0][jj], v[1][jj], v[2][jj], v[3][jj]);
    *(float4*)(dst+4) = make_float4(v[4][jj], v[5][jj], v[6][jj], v[7][jj]);
  }
}

// ---------- inner matmul with pre-splatted G, half-width h buffer ----------
// Warp tile 32c x 16b, thread tile 4c x 4b. 11 instr / 32 FMA.
// Acc layout (proven): a[r][0] = row c0+r x (b0,b0+1) ; a[r][1] = row c0+r x (b0+2,b0+3).
static __device__ __forceinline__ void mm_acc(const ull* __restrict__ sG,
    const float* __restrict__ hb, int c0, int bloc, ull a[4][2]){
  #pragma unroll 8
  for (int k = 0; k < CC; k++){
    ulonglong2 g01 = *(const ulonglong2*)(sG + k*GSU + c0);      // splat G[c0,k], G[c0+1,k]
    ulonglong2 g23 = *(const ulonglong2*)(sG + k*GSU + c0 + 2);  // splat G[c0+2,k], G[c0+3,k]
    ulonglong2 hq  = *(const ulonglong2*)(hb + k*HS2 + bloc);    // pairs (b,b+1),(b+2,b+3)
    fma2(a[0][0], g01.x, hq.x); fma2(a[0][1], g01.x, hq.y);
    fma2(a[1][0], g01.y, hq.x); fma2(a[1][1], g01.y, hq.y);
    fma2(a[2][0], g23.x, hq.x); fma2(a[2][1], g23.x, hq.y);
    fma2(a[3][0], g23.y, hq.x); fma2(a[3][1], g23.y, hq.y);
  }
}

// ---------- kernel 2: persistent column-pipelined DAG recurrence ----------
// CTA = (dir, column). 4 warps = 2 INDEPENDENT half-engines (warp-pair h owns b in [16h,16h+16)).
// warp w: half = w>>1, cpart = w&1. No __syncthreads in loop; named bars (64 thr) per half.
extern __shared__ float smem_dyn[];

__global__ void __launch_bounds__(128, 2) k_dag(
    const float* __restrict__ w0v, const float* __restrict__ w0h,
    const float* __restrict__ w1v, const float* __restrict__ w1h,
    const float* __restrict__ w2v, const float* __restrict__ w2h,
    const float* __restrict__ w3v, const float* __restrict__ w3h)
{
  const int bid  = blockIdx.x;
  const int dir  = bid / WW;        // dependency points to lower bids only -> schedule-safe
  const int jcol = bid % WW;
  const int tid  = threadIdx.x;

  const float* gv; const float* gh;
  int fi, fj, doRelu;
  switch (dir){
    case 0:  gv=w0v; gh=w0h; fi=0; fj=0; doRelu=1; break;  // SE
    case 1:  gv=w1v; gh=w1h; fi=1; fj=0; doRelu=1; break;  // NE
    case 2:  gv=w2v; gh=w2h; fi=1; fj=1; doRelu=1; break;  // NW
    default: gv=w3v; gh=w3h; fi=0; fj=1; doRelu=0; break;  // SW (no ReLU in reference)
  }

  ull*   sGv   = (ull*)smem_dyn;            // [k][c] splatted, CC*GSU ull
  ull*   sGh   = sGv + CC*GSU;
  float* hbase = (float*)(sGh + CC*GSU);    // per half: hA (CC*HS2), hB (CC*HS2); halves consecutive

  for (int idx = tid; idx < 4096; idx += 128){
    int c = idx >> 6, k = idx & 63;         // idx = c*64 + k (row-major source)
    sGv[k*GSU + c] = splat2(gv[idx]);
    sGh[k*GSU + c] = splat2(gh[idx]);
  }
  for (int idx = tid; idx < 4*CC*HS2; idx += 128) hbase[idx] = 0.f;  // zero all h buffers
  __syncthreads();                          // only CTA-wide bar (init)

  const int lane = tid & 31, w = tid >> 5;
  const int half = w >> 1, cpart = w & 1;
  const int cg = lane >> 2, bp = lane & 3;
  const int c0   = cpart*32 + cg*4;         // global c base of thread tile
  const int bloc = bp*4;                    // local b within half (0..12)
  const int b0g  = half*16 + bloc;          // global b
  const int tRow = cpart*32 + lane;         // staging row (this warp stages its producer's region)

  float* hA = hbase + (2*half + 0)*CC*HS2;  // half-private; single-buffer is safe (bar-ordered)
  float* hB = hbase + (2*half + 1)*CC*HS2;

  float* out_dir = g_hf[dir];
  const int rj  = fj ? (WW-1-jcol) : jcol;
  const int rjL = fj ? (WW-jcol)   : (jcol-1);
  const int* pflag = &g_cnt[dir][(jcol > 0) ? (jcol-1) : 0][w];  // left neighbor, SAME warp slot
  int* mflag = &g_cnt[dir][jcol][w];
  const int barid = 1 + half;

  // ---- prefetch x for row 0 ----
  ulonglong2 xp[4];
  {
    const int ri0 = fi ? (HH-1) : 0;
    const float* xc = g_xT + (ri0*WW + rj)*CELL;
    #pragma unroll
    for (int r = 0; r < 4; r++)
      xp[r] = *(const ulonglong2*)(xc + (c0+r)*BB + b0g);
  }

  for (int i = 0; i < HH; i++){
    const int ri = fi ? (HH-1-i) : i;

    // ---- acc init from prefetched x ----
    ull a[4][2];
    #pragma unroll
    for (int r = 0; r < 4; r++){ a[r][0] = xp[r].x; a[r][1] = xp[r].y; }

    // ---- vertical matmul (own half's previous row) ----
    mm_acc(sGv, hA, c0, bloc, a);

    // ---- wait own producer-warp flag, stage its 32c x 16b region ----
    if (jcol > 0){
      const int need = i + 1;
      while (ld_acq(pflag) < need) { }
      const float* src = out_dir + (ri*WW + rjL)*CELL + tRow*BB + half*16;
      float4 l0 = *(const float4*)(src);
      float4 l1 = *(const float4*)(src + 4);
      float4 l2 = *(const float4*)(src + 8);
      float4 l3 = *(const float4*)(src + 12);
      float* dst = hB + tRow*HS2;
      *(float4*)(dst + 0)  = l0;
      *(float4*)(dst + 4)  = l1;
      *(float4*)(dst + 8)  = l2;
      *(float4*)(dst + 12) = l3;
    }
    named_bar(barid);                        // half-bar: hB staged AND both warps' mmGv done

    // ---- prefetch x for next row (consumed next iteration; hidden under mmGh) ----
    {
      const int in  = (i+1 < HH) ? (i+1) : i;
      const int rin = fi ? (HH-1-in) : in;
      const float* xc = g_xT + (rin*WW + rj)*CELL;
      #pragma unroll
      for (int r = 0; r < 4; r++)
        xp[r] = *(const ulonglong2*)(xc + (c0+r)*BB + b0g);
    }

    if (jcol > 0)
      mm_acc(sGh, hB, c0, bloc, a);          // horizontal matmul

    // ---- epilogue: unpack, ReLU ----
    float o[4][4];                           // o[r][bb] = h[c0+r][b0g+bb]
    #pragma unroll
    for (int r = 0; r < 4; r++){
      unpack2(a[r][0], o[r][0], o[r][1]);
      unpack2(a[r][1], o[r][2], o[r][3]);
    }
    if (doRelu){
      #pragma unroll
      for (int r = 0; r < 4; r++)
        #pragma unroll
        for (int bb = 0; bb < 4; bb++)
          o[r][bb] = fmaxf(o[r][bb], 0.f);
    }

    // ---- publish to gmem, per-warp release flag ----
    float* ocell = out_dir + (ri*WW + rj)*CELL;
    #pragma unroll
    for (int r = 0; r < 4; r++)
      *(float4*)(ocell + (c0+r)*BB + b0g) = make_float4(o[r][0], o[r][1], o[r][2], o[r][3]);
    __syncwarp();                            // orders all lanes' STGs before lane0's release
    if (lane == 0) st_rel(mflag, i + 1);

    // ---- local writeback: next row's h_prev for this half ----
    #pragma unroll
    for (int r = 0; r < 4; r++)
      *(float4*)(hA + (c0+r)*HS2 + bloc) = make_float4(o[r][0], o[r][1], o[r][2], o[r][3]);
    named_bar(barid);                        // half-bar: hA(new) visible to both warps
  }
}

// ---------- kernel 3: out[b][c][i][j] = sum over 4 dirs of g_hf[d][i][j][c][b] ----------
__global__ void __launch_bounds__(256) k_sum(float* __restrict__ out){
  int bid = blockIdx.x;              // 800 blocks: (i, j-tile of 8)
  int i  = bid / 10;
  int j0 = (bid % 10) * 8;
  int t  = threadIdx.x;
  int p0 = t * 8;                    // fixed c, 8 consecutive b
  int c  = p0 >> 5;
  int b0 = p0 & 31;

  float v[8][8];
  #pragma unroll
  for (int jj = 0; jj < 8; jj++){
    int cell = (i*WW + j0 + jj)*CELL;
    float4 s0 = make_float4(0.f,0.f,0.f,0.f);
    float4 s1 = make_float4(0.f,0.f,0.f,0.f);
    #pragma unroll
    for (int d = 0; d < 4; d++){
      const float* src = g_hf[d] + cell + p0;
      float4 q0 = *(const float4*)src;
      float4 q1 = *(const float4*)(src + 4);
      s0.x += q0.x; s0.y += q0.y; s0.z += q0.z; s0.w += q0.w;
      s1.x += q1.x; s1.y += q1.y; s1.z += q1.z; s1.w += q1.w;
    }
    v[0][jj]=s0.x; v[1][jj]=s0.y; v[2][jj]=s0.z; v[3][jj]=s0.w;
    v[4][jj]=s1.x; v[5][jj]=s1.y; v[6][jj]=s1.z; v[7][jj]=s1.w;
  }
  #pragma unroll
  for (int pi = 0; pi < 8; pi++){
    float* dst = out + ((b0+pi)*CC + c)*NCELLS + i*WW + j0;
    *(float4*)dst     = make_float4(v[pi][0], v[pi][1], v[pi][2], v[pi][3]);
    *(float4*)(dst+4) = make_float4(v[pi][4], v[pi][5], v[pi][6], v[pi][7]);
  }
}

extern "C" void kernel_launch(void* const* d_in, const int* in_sizes, int n_in,
                              void* d_out, int out_size){
  const float* x   = (const float*)d_in[0];
  const float* g1  = (const float*)d_in[1];
  const float* g2  = (const float*)d_in[2];
  const float* g4  = (const float*)d_in[3];
  const float* g5  = (const float*)d_in[4];
  const float* g7  = (const float*)d_in[5];
  const float* g8  = (const float*)d_in[6];
  const float* g10 = (const float*)d_in[7];
  const float* g11 = (const float*)d_in[8];

  const int smem_bytes = 2*CC*GSU*8 + 4*CC*HS2*4;  // 67,584 + 20,480 = 88,064 B
  (void)cudaFuncSetAttribute(k_dag, cudaFuncAttributeMaxDynamicSharedMemorySize, smem_bytes);

  k_transpose<<<800, 256>>>(x);
  k_dag<<<320, 128, smem_bytes>>>(g1, g2, g4, g5, g7, g8, g10, g11);
  k_sum<<<800, 256>>>((float*)d_out);
}